// round 6
// baseline (speedup 1.0000x reference)
#include <cuda_runtime.h>
#include <cuda_bf16.h>
#include <math.h>
#include <stdint.h>

#define A_DIM 4608
#define L_DIM 4096
#define H_DIM 192
#define W_DIM 192
#define NTILE 36                 // A_DIM / 128 (M row tiles)
#define NBN   18                 // A_DIM / 256 (N col tiles)
#define BK    32
#define NIT   (3 * (L_DIM / BK))   // 384
#define PITCH 80                 // 32 bf16 = 64B + 16B pad
#define STAGE (384 * PITCH)      // A(128 rows) + B(256 rows) = 30720 B
#define NSTG  3
#define SMEM_BYTES (NSTG * STAGE)   // 92160

__device__ __nv_bfloat16 g_imgHi[(size_t)A_DIM * L_DIM];
__device__ __nv_bfloat16 g_imgLo[(size_t)A_DIM * L_DIM];
__device__ __nv_bfloat16 g_styHi[(size_t)A_DIM * L_DIM];
__device__ __nv_bfloat16 g_styLo[(size_t)A_DIM * L_DIM];
__device__ float g_invImg[A_DIM];
__device__ float g_invSty[A_DIM];
__device__ float g_pmax[NTILE * A_DIM];
__device__ int   g_pidx[NTILE * A_DIM];

__device__ __forceinline__ uint32_t smem_u32(const void* p) {
    uint32_t a;
    asm("{ .reg .u64 t; cvta.to.shared.u64 t, %1; cvt.u32.u64 %0, t; }" : "=r"(a) : "l"(p));
    return a;
}
#define CP16(dst, src) \
    asm volatile("cp.async.cg.shared.global [%0], [%1], 16;" :: "r"(dst), "l"(src) : "memory")
#define CP_COMMIT() asm volatile("cp.async.commit_group;" ::: "memory")
#define CP_WAIT1()  asm volatile("cp.async.wait_group 1;" ::: "memory")
#define CP_WAIT0()  asm volatile("cp.async.wait_group 0;" ::: "memory")
#define LDSM4(r0, r1, r2, r3, a) \
    asm volatile("ldmatrix.sync.aligned.m8n8.x4.shared.b16 {%0,%1,%2,%3}, [%4];" \
        : "=r"(r0), "=r"(r1), "=r"(r2), "=r"(r3) : "r"(a))
#define MMA_BF16(c, a, b) \
    asm volatile("mma.sync.aligned.m16n8k16.row.col.f32.bf16.bf16.f32 " \
        "{%0,%1,%2,%3}, {%4,%5,%6,%7}, {%8,%9}, {%0,%1,%2,%3};" \
        : "+f"((c)[0]), "+f"((c)[1]), "+f"((c)[2]), "+f"((c)[3]) \
        : "r"((a)[0]), "r"((a)[1]), "r"((a)[2]), "r"((a)[3]), "r"((b)[0]), "r"((b)[1]))

// ---------------------------------------------------------------------------
// 1) unfold + bf16 hi/lo split (block = (c, ph), coalesced both directions)
// ---------------------------------------------------------------------------
__global__ void __launch_bounds__(256)
unfold_split(const float* __restrict__ in, int which) {
    __shared__ float sh[576];
    const int c = blockIdx.x, ph = blockIdx.y;
    const float* src = in + ((size_t)c * H_DIM + ph * 3) * W_DIM;
    for (int i = threadIdx.x; i < 576; i += 256) sh[i] = src[i];
    __syncthreads();
    __nv_bfloat16* outHi = which ? g_styHi : g_imgHi;
    __nv_bfloat16* outLo = which ? g_styLo : g_imgLo;
    for (int i = threadIdx.x; i < 576; i += 256) {
        int seg = i >> 6;
        int pw  = i & 63;
        int kh = seg / 3, kw = seg - kh * 3;
        float v = sh[kh * W_DIM + pw * 3 + kw];
        __nv_bfloat16 hi = __float2bfloat16(v);
        __nv_bfloat16 lo = __float2bfloat16(v - __bfloat162float(hi));
        size_t o = ((size_t)c * 9 + seg) * L_DIM + ph * 64 + pw;
        outHi[o] = hi;
        outLo[o] = lo;
    }
}

// ---------------------------------------------------------------------------
// 2) row inverse norms
// ---------------------------------------------------------------------------
__global__ void norm_kernel() {
    const int row = blockIdx.x;
    const __nv_bfloat16* hi = (row < A_DIM) ? &g_imgHi[(size_t)row * L_DIM]
                                            : &g_styHi[(size_t)(row - A_DIM) * L_DIM];
    const __nv_bfloat16* lo = (row < A_DIM) ? &g_imgLo[(size_t)row * L_DIM]
                                            : &g_styLo[(size_t)(row - A_DIM) * L_DIM];
    float s = 0.0f;
    for (int i = threadIdx.x; i < L_DIM; i += 256) {
        float v = __bfloat162float(hi[i]) + __bfloat162float(lo[i]);
        s = fmaf(v, v, s);
    }
    __shared__ float sh[8];
    #pragma unroll
    for (int o = 16; o > 0; o >>= 1) s += __shfl_down_sync(0xffffffffu, s, o);
    if ((threadIdx.x & 31) == 0) sh[threadIdx.x >> 5] = s;
    __syncthreads();
    if (threadIdx.x < 32) {
        s = (threadIdx.x < 8) ? sh[threadIdx.x] : 0.0f;
        #pragma unroll
        for (int o = 4; o > 0; o >>= 1) s += __shfl_down_sync(0xffffffffu, s, o);
        if (threadIdx.x == 0) {
            float inv = 1.0f / sqrtf(s);
            if (row < A_DIM) g_invImg[row] = inv;
            else             g_invSty[row - A_DIM] = inv;
        }
    }
}

// ---------------------------------------------------------------------------
// 3) bf16x3 mma.sync GEMM, 128x256 tile, 512 threads (4x4 warps), BK=32,
//    3-stage cp.async ring, register column max/argmax epilogue.
// ---------------------------------------------------------------------------
__global__ void __launch_bounds__(512)
gemm_mma() {
    extern __shared__ char smem[];
    const uint32_t sb = smem_u32(smem);
    const int tid = threadIdx.x;
    const int wid = tid >> 5, lane = tid & 31;
    const int warp_m = wid & 3, warp_n = wid >> 2;     // 4 x 4
    const int m_base = warp_m * 32, n_base = warp_n * 64;
    const int bm = blockIdx.x, bn = blockIdx.y;
    const int m0 = bm * 128, n0 = bn * 256;

    const __nv_bfloat16* passA[3] = {
        g_styHi + (size_t)m0 * L_DIM, g_styHi + (size_t)m0 * L_DIM, g_styLo + (size_t)m0 * L_DIM };
    const __nv_bfloat16* passB[3] = {
        g_imgHi + (size_t)n0 * L_DIM, g_imgLo + (size_t)n0 * L_DIM, g_imgHi + (size_t)n0 * L_DIM };

    // cp.async: 384 rows x 4 chunks = 1536 chunks / 512 threads = 3 each
    auto issue = [&](int it, int s) {
        const int p = it / (L_DIM / BK);
        const int kx = (it % (L_DIM / BK)) * BK;
        const __nv_bfloat16* gA = passA[p] + kx;
        const __nv_bfloat16* gB = passB[p] + kx;
        const uint32_t st = sb + s * STAGE;
        #pragma unroll
        for (int u = 0; u < 3; ++u) {
            int idx = u * 512 + tid;
            int row = idx >> 2, col = idx & 3;
            const __nv_bfloat16* g = (row < 128)
                ? gA + (size_t)row * L_DIM + col * 8
                : gB + (size_t)(row - 128) * L_DIM + col * 8;
            CP16(st + row * PITCH + col * 16, g);
        }
        CP_COMMIT();
    };

    float acc[2][8][4];
    #pragma unroll
    for (int i = 0; i < 2; ++i)
        #pragma unroll
        for (int j = 0; j < 8; ++j)
            #pragma unroll
            for (int k = 0; k < 4; ++k) acc[i][j][k] = 0.0f;

    issue(0, 0);
    issue(1, 1);

    const uint32_t aOff = (uint32_t)(m_base + (lane & 15)) * PITCH + (lane >> 4) * 16;
    const uint32_t bOff = 128u * PITCH
                        + (uint32_t)(n_base + ((lane >> 4) * 8) + (lane & 7)) * PITCH
                        + (((lane >> 3) & 1) * 16);

    for (int it = 0; it < NIT; ++it) {
        const int s = it % NSTG;
        if (it + 2 < NIT) { CP_WAIT1(); } else { CP_WAIT0(); }
        __syncthreads();
        if (it + 2 < NIT) issue(it + 2, (it + 2) % NSTG);

        const uint32_t st = sb + s * STAGE;
        #pragma unroll
        for (int ks = 0; ks < 2; ++ks) {
            uint32_t a0[2][4];
            #pragma unroll
            for (int mt = 0; mt < 2; ++mt)
                LDSM4(a0[mt][0], a0[mt][1], a0[mt][2], a0[mt][3],
                      st + aOff + mt * 16 * PITCH + ks * 32);
            uint32_t b0[4][4];
            #pragma unroll
            for (int np = 0; np < 4; ++np)
                LDSM4(b0[np][0], b0[np][1], b0[np][2], b0[np][3],
                      st + bOff + np * 16 * PITCH + ks * 32);
            #pragma unroll
            for (int mt = 0; mt < 2; ++mt)
                #pragma unroll
                for (int np = 0; np < 4; ++np) {
                    MMA_BF16(acc[mt][np * 2],     a0[mt], (&b0[np][0]));
                    MMA_BF16(acc[mt][np * 2 + 1], a0[mt], (&b0[np][2]));
                }
        }
        __syncthreads();
    }

    // ---- register epilogue: column max of acc * invImg[row] ----
    float invR[4];
    #pragma unroll
    for (int mt = 0; mt < 2; ++mt)
        #pragma unroll
        for (int h = 0; h < 2; ++h)
            invR[mt * 2 + h] = g_invImg[m0 + m_base + mt * 16 + h * 8 + (lane >> 2)];

    float* pv = (float*)smem;                    // [4][256]
    int*   pi = (int*)(smem + 4 * 256 * 4);      // [4][256]
    __syncthreads();                             // reuse stage smem

    #pragma unroll
    for (int np = 0; np < 8; ++np)
        #pragma unroll
        for (int p = 0; p < 2; ++p) {
            float bv = -3.402823466e38f;
            int bi = 0x7fffffff;
            #pragma unroll
            for (int mt = 0; mt < 2; ++mt)        // rows ascending
                #pragma unroll
                for (int h = 0; h < 2; ++h) {
                    float v = acc[mt][np][h * 2 + p] * invR[mt * 2 + h];
                    int row = m0 + m_base + mt * 16 + h * 8 + (lane >> 2);
                    if (v > bv || (v == bv && row < bi)) { bv = v; bi = row; }
                }
            #pragma unroll
            for (int o = 4; o < 32; o <<= 1) {    // butterfly across lane>>2
                float ov = __shfl_xor_sync(0xffffffffu, bv, o);
                int   oi = __shfl_xor_sync(0xffffffffu, bi, o);
                if (ov > bv || (ov == bv && oi < bi)) { bv = ov; bi = oi; }
            }
            if ((lane >> 2) == 0) {
                int col = n_base + np * 8 + (lane & 3) * 2 + p;
                pv[warp_m * 256 + col] = bv;
                pi[warp_m * 256 + col] = bi;
            }
        }
    __syncthreads();

    if (tid < 256) {
        float bv = pv[tid];
        int bi = pi[tid];
        #pragma unroll
        for (int w = 1; w < 4; ++w) {             // ascending row groups
            float v = pv[w * 256 + tid];
            int  i2 = pi[w * 256 + tid];
            if (v > bv || (v == bv && i2 < bi)) { bv = v; bi = i2; }
        }
        g_pmax[bm * A_DIM + n0 + tid] = bv;
        g_pidx[bm * A_DIM + n0 + tid] = bi;
    }
}

// ---------------------------------------------------------------------------
// 4) final reduce over 36 row-tile partials
// ---------------------------------------------------------------------------
__global__ void final_kernel(float* __restrict__ out) {
    int j = blockIdx.x * blockDim.x + threadIdx.x;
    if (j >= A_DIM) return;
    float bv = g_pmax[j];
    int bi = g_pidx[j];
    #pragma unroll 4
    for (int t = 1; t < NTILE; ++t) {
        float v = g_pmax[t * A_DIM + j];
        int i = g_pidx[t * A_DIM + j];
        if (v > bv || (v == bv && i < bi)) { bv = v; bi = i; }
    }
    out[j]         = (float)bi;
    out[A_DIM + j] = bv * g_invSty[j];
}

// ---------------------------------------------------------------------------
extern "C" void kernel_launch(void* const* d_in, const int* in_sizes, int n_in,
                              void* d_out, int out_size) {
    const float* model = (const float*)d_in[0];
    const float* style = (const float*)d_in[1];
    float* out = (float*)d_out;

    cudaFuncSetAttribute(gemm_mma, cudaFuncAttributeMaxDynamicSharedMemorySize, SMEM_BYTES);

    unfold_split<<<dim3(512, 64), 256>>>(model, 0);
    unfold_split<<<dim3(512, 64), 256>>>(style, 1);
    norm_kernel<<<2 * A_DIM, 256>>>();
    gemm_mma<<<dim3(NTILE, NBN), 512, SMEM_BYTES>>>();
    final_kernel<<<A_DIM / 256, 256>>>(out);
}

// round 7
// speedup vs baseline: 1.2142x; 1.2142x over previous
#include <cuda_runtime.h>
#include <cuda_bf16.h>
#include <math.h>
#include <stdint.h>

#define A_DIM 4608
#define L_DIM 4096
#define H_DIM 192
#define W_DIM 192
#define NTILE 36                 // A_DIM / 128
#define BK    32
#define NIT   (3 * (L_DIM / BK))   // 384
#define PITCH 80                 // 32 bf16 = 64B + 16B pad
#define STAGE (256 * PITCH)      // A(128) + B(128) rows = 20480 B
#define NSTG  3
#define SMEM_BYTES (NSTG * STAGE)   // 61440

__device__ __nv_bfloat16 g_imgHi[(size_t)A_DIM * L_DIM];
__device__ __nv_bfloat16 g_imgLo[(size_t)A_DIM * L_DIM];
__device__ __nv_bfloat16 g_styHi[(size_t)A_DIM * L_DIM];
__device__ __nv_bfloat16 g_styLo[(size_t)A_DIM * L_DIM];
__device__ float g_invImg[A_DIM];
__device__ float g_invSty[A_DIM];
__device__ float g_pmax[NTILE * A_DIM];
__device__ int   g_pidx[NTILE * A_DIM];

__device__ __forceinline__ uint32_t smem_u32(const void* p) {
    uint32_t a;
    asm("{ .reg .u64 t; cvta.to.shared.u64 t, %1; cvt.u32.u64 %0, t; }" : "=r"(a) : "l"(p));
    return a;
}
#define CP16(dst, src) \
    asm volatile("cp.async.cg.shared.global [%0], [%1], 16;" :: "r"(dst), "l"(src) : "memory")
#define CP_COMMIT() asm volatile("cp.async.commit_group;" ::: "memory")
#define CP_WAIT1()  asm volatile("cp.async.wait_group 1;" ::: "memory")
#define CP_WAIT0()  asm volatile("cp.async.wait_group 0;" ::: "memory")
#define LDSM4(r0, r1, r2, r3, a) \
    asm volatile("ldmatrix.sync.aligned.m8n8.x4.shared.b16 {%0,%1,%2,%3}, [%4];" \
        : "=r"(r0), "=r"(r1), "=r"(r2), "=r"(r3) : "r"(a))
#define MMA_BF16(c, a, b) \
    asm volatile("mma.sync.aligned.m16n8k16.row.col.f32.bf16.bf16.f32 " \
        "{%0,%1,%2,%3}, {%4,%5,%6,%7}, {%8,%9}, {%0,%1,%2,%3};" \
        : "+f"((c)[0]), "+f"((c)[1]), "+f"((c)[2]), "+f"((c)[3]) \
        : "r"((a)[0]), "r"((a)[1]), "r"((a)[2]), "r"((a)[3]), "r"((b)[0]), "r"((b)[1]))

// ---------------------------------------------------------------------------
// 1) unfold + bf16 hi/lo split
// ---------------------------------------------------------------------------
__global__ void __launch_bounds__(256)
unfold_split(const float* __restrict__ in, int which) {
    __shared__ float sh[576];
    const int c = blockIdx.x, ph = blockIdx.y;
    const float* src = in + ((size_t)c * H_DIM + ph * 3) * W_DIM;
    for (int i = threadIdx.x; i < 576; i += 256) sh[i] = src[i];
    __syncthreads();
    __nv_bfloat16* outHi = which ? g_styHi : g_imgHi;
    __nv_bfloat16* outLo = which ? g_styLo : g_imgLo;
    for (int i = threadIdx.x; i < 576; i += 256) {
        int seg = i >> 6, pw = i & 63;
        int kh = seg / 3, kw = seg - kh * 3;
        float v = sh[kh * W_DIM + pw * 3 + kw];
        __nv_bfloat16 hi = __float2bfloat16(v);
        __nv_bfloat16 lo = __float2bfloat16(v - __bfloat162float(hi));
        size_t o = ((size_t)c * 9 + seg) * L_DIM + ph * 64 + pw;
        outHi[o] = hi;
        outLo[o] = lo;
    }
}

// ---------------------------------------------------------------------------
// 2) row inverse norms
// ---------------------------------------------------------------------------
__global__ void norm_kernel() {
    const int row = blockIdx.x;
    const __nv_bfloat16* hi = (row < A_DIM) ? &g_imgHi[(size_t)row * L_DIM]
                                            : &g_styHi[(size_t)(row - A_DIM) * L_DIM];
    const __nv_bfloat16* lo = (row < A_DIM) ? &g_imgLo[(size_t)row * L_DIM]
                                            : &g_styLo[(size_t)(row - A_DIM) * L_DIM];
    float s = 0.0f;
    for (int i = threadIdx.x; i < L_DIM; i += 256) {
        float v = __bfloat162float(hi[i]) + __bfloat162float(lo[i]);
        s = fmaf(v, v, s);
    }
    __shared__ float sh[8];
    #pragma unroll
    for (int o = 16; o > 0; o >>= 1) s += __shfl_down_sync(0xffffffffu, s, o);
    if ((threadIdx.x & 31) == 0) sh[threadIdx.x >> 5] = s;
    __syncthreads();
    if (threadIdx.x < 32) {
        s = (threadIdx.x < 8) ? sh[threadIdx.x] : 0.0f;
        #pragma unroll
        for (int o = 4; o > 0; o >>= 1) s += __shfl_down_sync(0xffffffffu, s, o);
        if (threadIdx.x == 0) {
            float inv = 1.0f / sqrtf(s);
            if (row < A_DIM) g_invImg[row] = inv;
            else             g_invSty[row - A_DIM] = inv;
        }
    }
}

// ---------------------------------------------------------------------------
// 3) bf16x3 mma.sync GEMM, 128x128 tile, 256 threads (4x2 warps), BK=32,
//    3-stage ring, ONE barrier/iter, register max/argmax epilogue. 2 CTAs/SM.
// ---------------------------------------------------------------------------
__global__ void __launch_bounds__(256, 2)
gemm_mma() {
    extern __shared__ char smem[];
    const uint32_t sb = smem_u32(smem);
    const int tid = threadIdx.x;
    const int wid = tid >> 5, lane = tid & 31;
    const int warp_m = wid & 3, warp_n = wid >> 2;     // 4 x 2
    const int m_base = warp_m * 32, n_base = warp_n * 64;
    const int bm = blockIdx.x, bn = blockIdx.y;
    const int m0 = bm * 128, n0 = bn * 128;

    const __nv_bfloat16* passA[3] = {
        g_styHi + (size_t)m0 * L_DIM, g_styHi + (size_t)m0 * L_DIM, g_styLo + (size_t)m0 * L_DIM };
    const __nv_bfloat16* passB[3] = {
        g_imgHi + (size_t)n0 * L_DIM, g_imgLo + (size_t)n0 * L_DIM, g_imgHi + (size_t)n0 * L_DIM };

    // 256 rows x 4 chunks = 1024 chunks / 256 threads = 4 each
    auto issue = [&](int it, int s) {
        const int p = it / (L_DIM / BK);
        const int kx = (it % (L_DIM / BK)) * BK;
        const __nv_bfloat16* gA = passA[p] + kx;
        const __nv_bfloat16* gB = passB[p] + kx;
        const uint32_t st = sb + s * STAGE;
        #pragma unroll
        for (int u = 0; u < 4; ++u) {
            int idx = u * 256 + tid;
            int row = idx >> 2, col = idx & 3;
            const __nv_bfloat16* g = (row < 128)
                ? gA + (size_t)row * L_DIM + col * 8
                : gB + (size_t)(row - 128) * L_DIM + col * 8;
            CP16(st + row * PITCH + col * 16, g);
        }
        CP_COMMIT();
    };

    float acc[2][8][4];
    #pragma unroll
    for (int i = 0; i < 2; ++i)
        #pragma unroll
        for (int j = 0; j < 8; ++j)
            #pragma unroll
            for (int k = 0; k < 4; ++k) acc[i][j][k] = 0.0f;

    issue(0, 0);
    issue(1, 1);

    const uint32_t aOff = (uint32_t)(m_base + (lane & 15)) * PITCH + (lane >> 4) * 16;
    const uint32_t bOff = 128u * PITCH
                        + (uint32_t)(n_base + ((lane >> 4) * 8) + (lane & 7)) * PITCH
                        + (((lane >> 3) & 1) * 16);

    for (int it = 0; it < NIT; ++it) {
        const int s = it % NSTG;
        if (it + 2 < NIT) { CP_WAIT1(); } else { CP_WAIT0(); }
        __syncthreads();                       // single barrier per iteration
        if (it + 2 < NIT) issue(it + 2, (it + 2) % NSTG);

        const uint32_t st = sb + s * STAGE;
        // front-load all ldmatrix for both ks halves
        uint32_t a0[2][2][4], b0[2][4][4];
        #pragma unroll
        for (int ks = 0; ks < 2; ++ks) {
            #pragma unroll
            for (int mt = 0; mt < 2; ++mt)
                LDSM4(a0[ks][mt][0], a0[ks][mt][1], a0[ks][mt][2], a0[ks][mt][3],
                      st + aOff + mt * 16 * PITCH + ks * 32);
            #pragma unroll
            for (int np = 0; np < 4; ++np)
                LDSM4(b0[ks][np][0], b0[ks][np][1], b0[ks][np][2], b0[ks][np][3],
                      st + bOff + np * 16 * PITCH + ks * 32);
        }
        #pragma unroll
        for (int ks = 0; ks < 2; ++ks)
            #pragma unroll
            for (int mt = 0; mt < 2; ++mt)
                #pragma unroll
                for (int np = 0; np < 4; ++np) {
                    MMA_BF16(acc[mt][np * 2],     a0[ks][mt], (&b0[ks][np][0]));
                    MMA_BF16(acc[mt][np * 2 + 1], a0[ks][mt], (&b0[ks][np][2]));
                }
    }

    // ---- register epilogue: column max of acc * invImg[row] ----
    float invR[4];
    #pragma unroll
    for (int mt = 0; mt < 2; ++mt)
        #pragma unroll
        for (int h = 0; h < 2; ++h)
            invR[mt * 2 + h] = g_invImg[m0 + m_base + mt * 16 + h * 8 + (lane >> 2)];

    float* pv = (float*)smem;                  // [4][128]
    int*   pi = (int*)(smem + 4 * 128 * 4);    // [4][128]
    __syncthreads();                           // safe to reuse ring smem

    #pragma unroll
    for (int np = 0; np < 8; ++np)
        #pragma unroll
        for (int p = 0; p < 2; ++p) {
            float bv = -3.402823466e38f;
            int bi = 0x7fffffff;
            #pragma unroll
            for (int mt = 0; mt < 2; ++mt)
                #pragma unroll
                for (int h = 0; h < 2; ++h) {
                    float v = acc[mt][np][h * 2 + p] * invR[mt * 2 + h];
                    int row = m0 + m_base + mt * 16 + h * 8 + (lane >> 2);
                    if (v > bv || (v == bv && row < bi)) { bv = v; bi = row; }
                }
            #pragma unroll
            for (int o = 4; o < 32; o <<= 1) {
                float ov = __shfl_xor_sync(0xffffffffu, bv, o);
                int   oi = __shfl_xor_sync(0xffffffffu, bi, o);
                if (ov > bv || (ov == bv && oi < bi)) { bv = ov; bi = oi; }
            }
            if ((lane >> 2) == 0) {
                int col = n_base + np * 8 + (lane & 3) * 2 + p;
                pv[warp_m * 128 + col] = bv;
                pi[warp_m * 128 + col] = bi;
            }
        }
    __syncthreads();

    if (tid < 128) {
        float bv = pv[tid];
        int bi = pi[tid];
        #pragma unroll
        for (int w = 1; w < 4; ++w) {
            float v = pv[w * 128 + tid];
            int  i2 = pi[w * 128 + tid];
            if (v > bv || (v == bv && i2 < bi)) { bv = v; bi = i2; }
        }
        g_pmax[bm * A_DIM + n0 + tid] = bv;
        g_pidx[bm * A_DIM + n0 + tid] = bi;
    }
}

// ---------------------------------------------------------------------------
// 4) final reduce
// ---------------------------------------------------------------------------
__global__ void final_kernel(float* __restrict__ out) {
    int j = blockIdx.x * blockDim.x + threadIdx.x;
    if (j >= A_DIM) return;
    float bv = g_pmax[j];
    int bi = g_pidx[j];
    #pragma unroll 4
    for (int t = 1; t < NTILE; ++t) {
        float v = g_pmax[t * A_DIM + j];
        int i = g_pidx[t * A_DIM + j];
        if (v > bv || (v == bv && i < bi)) { bv = v; bi = i; }
    }
    out[j]         = (float)bi;
    out[A_DIM + j] = bv * g_invSty[j];
}

// ---------------------------------------------------------------------------
extern "C" void kernel_launch(void* const* d_in, const int* in_sizes, int n_in,
                              void* d_out, int out_size) {
    const float* model = (const float*)d_in[0];
    const float* style = (const float*)d_in[1];
    float* out = (float*)d_out;

    cudaFuncSetAttribute(gemm_mma, cudaFuncAttributeMaxDynamicSharedMemorySize, SMEM_BYTES);

    unfold_split<<<dim3(512, 64), 256>>>(model, 0);
    unfold_split<<<dim3(512, 64), 256>>>(style, 1);
    norm_kernel<<<2 * A_DIM, 256>>>();
    gemm_mma<<<dim3(NTILE, NTILE), 256, SMEM_BYTES>>>();
    final_kernel<<<A_DIM / 256, 256>>>(out);
}

// round 8
// speedup vs baseline: 1.4729x; 1.2130x over previous
#include <cuda_runtime.h>
#include <cuda_fp16.h>
#include <math.h>
#include <stdint.h>

#define A_DIM 4608
#define L_DIM 4096
#define H_DIM 192
#define W_DIM 192
#define NTILE 36                 // A_DIM / 128
#define BK    32
#define NIT   (3 * (L_DIM / BK))   // 384
#define PITCH 80                 // 32 fp16 = 64B + 16B pad
#define STAGE (256 * PITCH)      // A(128) + B(128) rows = 20480 B
#define NSTG  3
#define SMEM_BYTES (NSTG * STAGE)   // 61440

__device__ __half g_imgHi[(size_t)A_DIM * L_DIM];
__device__ __half g_imgLo[(size_t)A_DIM * L_DIM];
__device__ __half g_styHi[(size_t)A_DIM * L_DIM];
__device__ __half g_styLo[(size_t)A_DIM * L_DIM];
__device__ float g_invImg[A_DIM];
__device__ float g_invSty[A_DIM];
__device__ float g_pmax[NTILE * A_DIM];
__device__ int   g_pidx[NTILE * A_DIM];

__device__ __forceinline__ uint32_t smem_u32(const void* p) {
    uint32_t a;
    asm("{ .reg .u64 t; cvta.to.shared.u64 t, %1; cvt.u32.u64 %0, t; }" : "=r"(a) : "l"(p));
    return a;
}
#define CP16(dst, src) \
    asm volatile("cp.async.cg.shared.global [%0], [%1], 16;" :: "r"(dst), "l"(src) : "memory")
#define CP_COMMIT() asm volatile("cp.async.commit_group;" ::: "memory")
#define CP_WAIT1()  asm volatile("cp.async.wait_group 1;" ::: "memory")
#define CP_WAIT0()  asm volatile("cp.async.wait_group 0;" ::: "memory")
#define LDSM4(r0, r1, r2, r3, a) \
    asm volatile("ldmatrix.sync.aligned.m8n8.x4.shared.b16 {%0,%1,%2,%3}, [%4];" \
        : "=r"(r0), "=r"(r1), "=r"(r2), "=r"(r3) : "r"(a))
#define MMA_F16(c, a, b) \
    asm volatile("mma.sync.aligned.m16n8k16.row.col.f32.f16.f16.f32 " \
        "{%0,%1,%2,%3}, {%4,%5,%6,%7}, {%8,%9}, {%0,%1,%2,%3};" \
        : "+f"((c)[0]), "+f"((c)[1]), "+f"((c)[2]), "+f"((c)[3]) \
        : "r"((a)[0]), "r"((a)[1]), "r"((a)[2]), "r"((a)[3]), "r"((b)[0]), "r"((b)[1]))

// ---------------------------------------------------------------------------
// 1) unfold + fp16 hi/lo split + fused row norms (block = channel c).
//    Norms computed from exact fp32 input, deterministic ordered reduction.
// ---------------------------------------------------------------------------
__global__ void __launch_bounds__(192)
unfold_norm(const float* __restrict__ in, int which) {
    __shared__ float sh[576];
    __shared__ float red[9][64];
    const int c = blockIdx.x;
    const int tid = threadIdx.x;
    const float* src = in + (size_t)c * H_DIM * W_DIM;
    __half* outHi = which ? g_styHi : g_imgHi;
    __half* outLo = which ? g_styLo : g_imgLo;

    float acc0 = 0.0f, acc1 = 0.0f, acc2 = 0.0f;
    for (int ph = 0; ph < 64; ++ph) {
        const float* rsrc = src + ph * 3 * W_DIM;
        sh[tid]       = rsrc[tid];
        sh[tid + 192] = rsrc[tid + 192];
        sh[tid + 384] = rsrc[tid + 384];
        __syncthreads();
        #pragma unroll
        for (int j = 0; j < 3; ++j) {
            int i = tid + j * 192;
            int seg = i >> 6, pw = i & 63;
            int kh = seg / 3, kw = seg - kh * 3;
            float v = sh[kh * W_DIM + pw * 3 + kw];
            __half hi = __float2half_rn(v);
            __half lo = __float2half_rn(v - __half2float(hi));
            size_t o = ((size_t)c * 9 + seg) * L_DIM + ph * 64 + pw;
            outHi[o] = hi;
            outLo[o] = lo;
            if (j == 0) acc0 = fmaf(v, v, acc0);
            else if (j == 1) acc1 = fmaf(v, v, acc1);
            else acc2 = fmaf(v, v, acc2);
        }
        __syncthreads();
    }
    red[(tid >> 6)][tid & 63]     = acc0;   // segs 0..2
    red[3 + (tid >> 6)][tid & 63] = acc1;   // segs 3..5
    red[6 + (tid >> 6)][tid & 63] = acc2;   // segs 6..8
    __syncthreads();
    if (tid < 9) {
        float s = 0.0f;
        #pragma unroll 8
        for (int k = 0; k < 64; ++k) s += red[tid][k];
        float inv = 1.0f / sqrtf(s);
        if (which) g_invSty[c * 9 + tid] = inv;
        else       g_invImg[c * 9 + tid] = inv;
    }
}

// ---------------------------------------------------------------------------
// 2) fp16x3 mma.sync GEMM: 128x128 tile, 4 warps (2x2), 64x64 per warp,
//    BK=32, 3-stage cp.async ring, register max/argmax epilogue. 2 CTAs/SM.
// ---------------------------------------------------------------------------
__global__ void __launch_bounds__(128, 2)
gemm_mma() {
    extern __shared__ char smem[];
    const uint32_t sb = smem_u32(smem);
    const int tid = threadIdx.x;
    const int wid = tid >> 5, lane = tid & 31;
    const int warp_m = wid & 1, warp_n = wid >> 1;     // 2 x 2
    const int m_base = warp_m * 64, n_base = warp_n * 64;
    const int bm = blockIdx.x, bn = blockIdx.y;
    const int m0 = bm * 128, n0 = bn * 128;

    const __half* passA[3] = {
        g_styHi + (size_t)m0 * L_DIM, g_styHi + (size_t)m0 * L_DIM, g_styLo + (size_t)m0 * L_DIM };
    const __half* passB[3] = {
        g_imgHi + (size_t)n0 * L_DIM, g_imgLo + (size_t)n0 * L_DIM, g_imgHi + (size_t)n0 * L_DIM };

    // 256 rows x 4 chunks = 1024 chunks / 128 threads = 8 each
    auto issue = [&](int it, int s) {
        const int p = it / (L_DIM / BK);
        const int kx = (it % (L_DIM / BK)) * BK;
        const __half* gA = passA[p] + kx;
        const __half* gB = passB[p] + kx;
        const uint32_t st = sb + s * STAGE;
        #pragma unroll
        for (int u = 0; u < 8; ++u) {
            int idx = u * 128 + tid;
            int row = idx >> 2, col = idx & 3;
            const __half* g = (row < 128)
                ? gA + (size_t)row * L_DIM + col * 8
                : gB + (size_t)(row - 128) * L_DIM + col * 8;
            CP16(st + row * PITCH + col * 16, g);
        }
        CP_COMMIT();
    };

    float acc[4][8][4];
    #pragma unroll
    for (int i = 0; i < 4; ++i)
        #pragma unroll
        for (int j = 0; j < 8; ++j)
            #pragma unroll
            for (int k = 0; k < 4; ++k) acc[i][j][k] = 0.0f;

    issue(0, 0);
    issue(1, 1);

    const uint32_t aOff = (uint32_t)(m_base + (lane & 15)) * PITCH + (lane >> 4) * 16;
    const uint32_t bOff = 128u * PITCH
                        + (uint32_t)(n_base + ((lane >> 4) * 8) + (lane & 7)) * PITCH
                        + (((lane >> 3) & 1) * 16);

    for (int it = 0; it < NIT; ++it) {
        const int s = it % NSTG;
        if (it + 2 < NIT) { CP_WAIT1(); } else { CP_WAIT0(); }
        __syncthreads();
        if (it + 2 < NIT) issue(it + 2, (it + 2) % NSTG);

        const uint32_t st = sb + s * STAGE;
        #pragma unroll
        for (int ks = 0; ks < 2; ++ks) {
            uint32_t a0[4][4];
            #pragma unroll
            for (int mt = 0; mt < 4; ++mt)
                LDSM4(a0[mt][0], a0[mt][1], a0[mt][2], a0[mt][3],
                      st + aOff + mt * 16 * PITCH + ks * 32);
            uint32_t b0[4][4];
            #pragma unroll
            for (int np = 0; np < 4; ++np)
                LDSM4(b0[np][0], b0[np][1], b0[np][2], b0[np][3],
                      st + bOff + np * 16 * PITCH + ks * 32);
            #pragma unroll
            for (int mt = 0; mt < 4; ++mt)
                #pragma unroll
                for (int np = 0; np < 4; ++np) {
                    MMA_F16(acc[mt][np * 2],     a0[mt], (&b0[np][0]));
                    MMA_F16(acc[mt][np * 2 + 1], a0[mt], (&b0[np][2]));
                }
        }
        __syncthreads();
    }

    // ---- register epilogue: column max of acc * invImg[row] ----
    float invR[8];
    #pragma unroll
    for (int mt = 0; mt < 4; ++mt)
        #pragma unroll
        for (int h = 0; h < 2; ++h)
            invR[mt * 2 + h] = g_invImg[m0 + m_base + mt * 16 + h * 8 + (lane >> 2)];

    float* pv = (float*)smem;                  // [2][128]
    int*   pi = (int*)(smem + 2 * 128 * 4);    // [2][128]
    __syncthreads();                           // ring smem dead; reuse

    #pragma unroll
    for (int j = 0; j < 8; ++j)
        #pragma unroll
        for (int p = 0; p < 2; ++p) {
            float bv = -3.402823466e38f;
            int bi = 0x7fffffff;
            #pragma unroll
            for (int mt = 0; mt < 4; ++mt)      // rows ascending
                #pragma unroll
                for (int h = 0; h < 2; ++h) {
                    float v = acc[mt][j][h * 2 + p] * invR[mt * 2 + h];
                    int row = m0 + m_base + mt * 16 + h * 8 + (lane >> 2);
                    if (v > bv || (v == bv && row < bi)) { bv = v; bi = row; }
                }
            #pragma unroll
            for (int o = 4; o < 32; o <<= 1) {  // butterfly across lane>>2
                float ov = __shfl_xor_sync(0xffffffffu, bv, o);
                int   oi = __shfl_xor_sync(0xffffffffu, bi, o);
                if (ov > bv || (ov == bv && oi < bi)) { bv = ov; bi = oi; }
            }
            if ((lane >> 2) == 0) {
                int col = n_base + j * 8 + (lane & 3) * 2 + p;
                pv[warp_m * 128 + col] = bv;
                pi[warp_m * 128 + col] = bi;
            }
        }
    __syncthreads();

    if (tid < 128) {
        float bv = pv[tid];
        int bi = pi[tid];
        float v = pv[128 + tid];
        int  i2 = pi[128 + tid];
        if (v > bv || (v == bv && i2 < bi)) { bv = v; bi = i2; }
        g_pmax[bm * A_DIM + n0 + tid] = bv;
        g_pidx[bm * A_DIM + n0 + tid] = bi;
    }
}

// ---------------------------------------------------------------------------
// 3) final reduce over 36 row-tile partials
// ---------------------------------------------------------------------------
__global__ void final_kernel(float* __restrict__ out) {
    int j = blockIdx.x * blockDim.x + threadIdx.x;
    if (j >= A_DIM) return;
    float bv = g_pmax[j];
    int bi = g_pidx[j];
    #pragma unroll 4
    for (int t = 1; t < NTILE; ++t) {
        float v = g_pmax[t * A_DIM + j];
        int i = g_pidx[t * A_DIM + j];
        if (v > bv || (v == bv && i < bi)) { bv = v; bi = i; }
    }
    out[j]         = (float)bi;
    out[A_DIM + j] = bv * g_invSty[j];
}

// ---------------------------------------------------------------------------
extern "C" void kernel_launch(void* const* d_in, const int* in_sizes, int n_in,
                              void* d_out, int out_size) {
    const float* model = (const float*)d_in[0];
    const float* style = (const float*)d_in[1];
    float* out = (float*)d_out;

    cudaFuncSetAttribute(gemm_mma, cudaFuncAttributeMaxDynamicSharedMemorySize, SMEM_BYTES);

    unfold_norm<<<512, 192>>>(model, 0);
    unfold_norm<<<512, 192>>>(style, 1);
    gemm_mma<<<dim3(NTILE, NTILE), 128, SMEM_BYTES>>>();
    final_kernel<<<A_DIM / 256, 256>>>(out);
}